// round 14
// baseline (speedup 1.0000x reference)
#include <cuda_runtime.h>
#include <math.h>
#include <stdint.h>

// LSTM cell B=4096, IN=H=1024 — int8 Karatsuba-Ozaki GEMM on IMMA m16n8k32,
// fused LSTM epilogue, 2 CTAs/SM.
// R14: warp-specialized producer — warp 8 issues ALL cp.async; warps 0-7 are
// pure ldsm+imma consumers (R11 inner loop). Sole-copier CP_WAIT(1) + uniform
// per-ktile __syncthreads gives visibility; empty-group commits keep the
// wait accounting exact through the drain.
// Quantize: V = round(v * 2031 / scale), V = 17*D1 + D2 (|D1|<=119, |D2|<=8).
// Planes: S1 = D1, S2 = D1 + D2 (|S2| <= 127).
//   17*(16*P1 + P2) = V*W + 16*D2a*D2b   (dropped term ~2.5e-4 rel)
// GEMM tile: M=128 x N=128, N = same 32 output columns of all 4 gates
// (smem B row r <-> gate r>>5, col col0+(r&31)).

#define BM 128
#define BN 128
#define KTILES 32
#define STAGES 3
#define THREADS 288                     // 8 consumer warps + 1 producer warp
#define A_STAGE_BYTES (BM * 128)        // 16384
#define B_STAGE_BYTES (BN * 128)        // 16384
#define STAGE_BYTES (A_STAGE_BYTES + B_STAGE_BYTES)   // 32768
#define SMEM_DYN (STAGES * STAGE_BYTES)               // 98304
#define PSTRIDE 132                     // floats per staged row (128 + pad)

#define VMAXF 2031.0f
#define SBSCALE (17.0f / (VMAXF * VMAXF))

static __device__ __align__(16) int8_t g_Aq[4096ull * 4096];  // [m][S1|S2]
static __device__ __align__(16) int8_t g_Bq[4096ull * 4096];  // [n=g*1024+c][T1|T2]
static __device__ float g_sa[4096];          // row max (raw)
static __device__ unsigned g_cmax[4096];     // col max |W| as float bits

// ---------------- PTX helpers (baseline sm_80 ISA) ----------------
__device__ __forceinline__ uint32_t smem_u32(const void* p) {
    return (uint32_t)__cvta_generic_to_shared(p);
}
__device__ __forceinline__ void cp16(uint32_t dst, const void* src) {
    asm volatile("cp.async.cg.shared.global [%0], [%1], 16;\n" :: "r"(dst), "l"(src));
}
__device__ __forceinline__ void cp_commit() {
    asm volatile("cp.async.commit_group;\n" ::: "memory");
}
#define CP_WAIT(N) asm volatile("cp.async.wait_group %0;\n" :: "n"(N) : "memory")

__device__ __forceinline__ void ldsm_x4(uint32_t* r, uint32_t addr) {
    asm volatile("ldmatrix.sync.aligned.m8n8.x4.shared.b16 {%0,%1,%2,%3}, [%4];\n"
                 : "=r"(r[0]), "=r"(r[1]), "=r"(r[2]), "=r"(r[3]) : "r"(addr));
}
__device__ __forceinline__ void imma16832(int* c, const uint32_t* a,
                                          uint32_t b0, uint32_t b1) {
    asm volatile(
        "mma.sync.aligned.m16n8k32.row.col.s32.s8.s8.s32 "
        "{%0,%1,%2,%3}, {%4,%5,%6,%7}, {%8,%9}, {%0,%1,%2,%3};\n"
        : "+r"(c[0]), "+r"(c[1]), "+r"(c[2]), "+r"(c[3])
        : "r"(a[0]), "r"(a[1]), "r"(a[2]), "r"(a[3]), "r"(b0), "r"(b1));
}

// Karatsuba digit split: S1 = D1, S2 = D1 + D2 for V = 17*D1 + D2.
__device__ __forceinline__ void kdigits(float val, float inv, char& s1, char& s2) {
    int vi = __float2int_rn(val * inv);                   // |vi| <= 2031
    int d1 = __float2int_rn((float)vi * (1.0f / 17.0f));  // |d1| <= 119
    int d2 = vi - 17 * d1;                                // |d2| <= 8
    s1 = (char)d1;
    s2 = (char)(d1 + d2);                                 // |.| <= 127
}

// Fast activations (MUFU-based, rel err ~1e-6, negligible vs 4.7e-4 quant).
__device__ __forceinline__ float sigf(float z) {
    return __fdividef(1.0f, 1.0f + __expf(-z));
}
__device__ __forceinline__ float tanhfast(float z) {
    return __fdividef(2.0f, 1.0f + __expf(-2.0f * z)) - 1.0f;
}

// ---------------- activation quantization (1-barrier version) ----------------
__global__ __launch_bounds__(256)
void quant_hx(const float* __restrict__ x, const float* __restrict__ h) {
    __shared__ float wmax[8];
    const int m = blockIdx.x;
    const int t = threadIdx.x;
    const int lane = t & 31, wid = t >> 5;
    const float* src = (t < 128) ? (x + (size_t)m * 1024 + t * 8)
                                 : (h + (size_t)m * 1024 + (t - 128) * 8);
    float4 v0 = *(const float4*)src;
    float4 v1 = *(const float4*)(src + 4);
    float vals[8] = {v0.x, v0.y, v0.z, v0.w, v1.x, v1.y, v1.z, v1.w};
    float mx = 0.0f;
    #pragma unroll
    for (int j = 0; j < 8; ++j) mx = fmaxf(mx, fabsf(vals[j]));
    #pragma unroll
    for (int o = 16; o > 0; o >>= 1)
        mx = fmaxf(mx, __shfl_xor_sync(0xffffffffu, mx, o));
    if (lane == 0) wmax[wid] = mx;
    __syncthreads();
    float sa = wmax[0];
    #pragma unroll
    for (int j = 1; j < 8; ++j) sa = fmaxf(sa, wmax[j]);
    sa = fmaxf(sa, 1e-30f);
    if (t == 0) g_sa[m] = sa;
    const float inv = VMAXF / sa;
    char d1[8], d2[8];
    #pragma unroll
    for (int j = 0; j < 8; ++j) kdigits(vals[j], inv, d1[j], d2[j]);
    size_t base = (size_t)m * 4096 + t * 8;
    *(uint2*)&g_Aq[base]        = *(uint2*)d1;   // S1 plane
    *(uint2*)&g_Aq[base + 2048] = *(uint2*)d2;   // S2 plane
}

// ---------------- weight quantization (2-pass, parallel) ----------------
__global__ __launch_bounds__(256)
void colmax_w(const float* __restrict__ Wf, const float* __restrict__ Wi,
              const float* __restrict__ Ws, const float* __restrict__ Wp) {
    __shared__ float red[8][33];
    const int g = blockIdx.z;
    const float* __restrict__ W = (g == 0) ? Wf : (g == 1) ? Wi : (g == 2) ? Ws : Wp;
    const int n0 = blockIdx.x * 32;
    const int k0 = blockIdx.y * 256;
    const int tx = threadIdx.x & 31;
    const int tk = threadIdx.x >> 5;   // 0..7

    float mx = 0.0f;
    #pragma unroll 8
    for (int i = 0; i < 32; ++i) {
        int k = k0 + tk + i * 8;
        mx = fmaxf(mx, fabsf(W[(size_t)k * 1024 + n0 + tx]));
    }
    red[tk][tx] = mx;
    __syncthreads();
    if (tk == 0) {
        float m = red[0][tx];
        #pragma unroll
        for (int j = 1; j < 8; ++j) m = fmaxf(m, red[j][tx]);
        atomicMax((int*)&g_cmax[g * 1024 + n0 + tx], __float_as_int(m));
    }
}

__global__ __launch_bounds__(256)
void quant_w2(const float* __restrict__ Wf, const float* __restrict__ Wi,
              const float* __restrict__ Ws, const float* __restrict__ Wp) {
    __shared__ __align__(8) char t1[32][64];
    __shared__ __align__(8) char t2[32][64];
    const int g = blockIdx.z;
    const float* __restrict__ W = (g == 0) ? Wf : (g == 1) ? Wi : (g == 2) ? Ws : Wp;
    const int n0 = blockIdx.x * 32;
    const int kt = blockIdx.y * 64;
    const int tx = threadIdx.x & 31;
    const int tk = threadIdx.x >> 5;   // 0..7

    const float cm = fmaxf(__int_as_float((int)g_cmax[g * 1024 + n0 + tx]), 1e-30f);
    const float inv = VMAXF / cm;

    #pragma unroll
    for (int j = 0; j < 8; ++j) {
        int k = kt + tk * 8 + j;
        char s1, s2;
        kdigits(W[(size_t)k * 1024 + n0 + tx], inv, s1, s2);
        t1[tx][tk * 8 + j] = s1;
        t2[tx][tk * 8 + j] = s2;
    }
    __syncthreads();
    const int r = threadIdx.x >> 3, seg = threadIdx.x & 7;
    size_t row = (size_t)(g * 1024 + n0 + r) * 4096;
    *(uint2*)&g_Bq[row + kt + seg * 8]        = *(uint2*)&t1[r][seg * 8];
    *(uint2*)&g_Bq[row + 2048 + kt + seg * 8] = *(uint2*)&t2[r][seg * 8];
}

// ---------------- fused IMMA GEMM + LSTM eltwise ----------------
__device__ __forceinline__ int koff(int kt) {
    return (kt < 16) ? (kt << 7) : (2048 + ((kt - 16) << 7));
}

// Producer-warp stage load: 32 lanes cover A (1024 cp16) + B (1024 cp16).
__device__ __forceinline__ void load_stage_p(uint32_t sbase, int stage, int m0,
                                             int col0, int lane) {
    const uint32_t sb = sbase + (uint32_t)(stage % STAGES) * STAGE_BYTES;
    const int kk = koff(stage);
    const int c = lane & 7;                    // const per lane
    const int r0 = lane >> 3;                  // 0..3
    #pragma unroll 8
    for (int j = 0; j < 32; ++j) {             // A: 128 rows x 128B
        int r = j * 4 + r0;
        uint32_t dst = sb + (uint32_t)(r * 128 + ((c ^ (r & 7)) * 16));
        cp16(dst, g_Aq + ((size_t)(m0 + r) * 4096 + kk + c * 16));
    }
    #pragma unroll 8
    for (int j = 0; j < 32; ++j) {             // B: 128 rows x 128B
        int r = j * 4 + r0;
        int nrow = ((r >> 5) << 10) + col0 + (r & 31);
        uint32_t dst = sb + (uint32_t)A_STAGE_BYTES
                     + (uint32_t)(r * 128 + ((c ^ (r & 7)) * 16));
        cp16(dst, g_Bq + ((size_t)nrow * 4096 + kk + c * 16));
    }
}

__global__ __launch_bounds__(THREADS, 2)
void gemm_fused(const float* __restrict__ cin,
                const float* __restrict__ bf, const float* __restrict__ bi,
                const float* __restrict__ bs, const float* __restrict__ bp,
                float* __restrict__ out) {
    extern __shared__ char dyn[];
    const uint32_t sbase = smem_u32(dyn);

    const int tid = threadIdx.x;
    const int wid = tid >> 5;
    const int lane = tid & 31;
    const int warp_m = wid & 3;                // consumers: 4 slabs x 32 rows
    const int warp_n = (wid >> 2) & 1;         // consumers: 0..1, 64-col slab
    const int m0 = blockIdx.y * BM;
    const int col0 = blockIdx.x * 32;          // output columns col0..col0+31

    const int lrow = lane & 15;
    const int lhi  = lane >> 4;

    int acc[2][8][4];
    #pragma unroll
    for (int mi = 0; mi < 2; ++mi)
        #pragma unroll
        for (int nj = 0; nj < 8; ++nj)
            #pragma unroll
            for (int q = 0; q < 4; ++q) acc[mi][nj][q] = 0;

    // Prologue: producer fills stages 0,1 and ensures stage 0 resident.
    if (wid == 8) {
        load_stage_p(sbase, 0, m0, col0, lane); cp_commit();
        load_stage_p(sbase, 1, m0, col0, lane); cp_commit();
        CP_WAIT(1);                            // stage 0 landed
    }
    __syncthreads();

    for (int kt = 0; kt < KTILES; ++kt) {
        if (wid == 8) {
            // Producer: issue stage kt+2, then guarantee stage kt+1 resident.
            if (kt + 2 < KTILES) load_stage_p(sbase, kt + 2, m0, col0, lane);
            cp_commit();                       // empty group when nothing issued
            CP_WAIT(1);                        // all but newest group complete
        } else {
            if (kt == 16) {                    // acc = 16*P1; continue with P2
                #pragma unroll
                for (int mi = 0; mi < 2; ++mi)
                    #pragma unroll
                    for (int nj = 0; nj < 8; ++nj)
                        #pragma unroll
                        for (int q = 0; q < 4; ++q) acc[mi][nj][q] <<= 4;
            }

            const uint32_t sA = sbase + (uint32_t)(kt % STAGES) * STAGE_BYTES;
            const uint32_t sB = sA + A_STAGE_BYTES;

            #pragma unroll
            for (int ks = 0; ks < 4; ++ks) {   // 4 x k32 per 128B stage
                const int kc = ks * 2 + lhi;   // 16B chunk 0..7
                uint32_t a[2][4];
                #pragma unroll
                for (int mi = 0; mi < 2; ++mi) {
                    int r = warp_m * 32 + mi * 16 + lrow;
                    uint32_t addr = sA + (uint32_t)(r * 128 + ((kc ^ (r & 7)) * 16));
                    ldsm_x4(a[mi], addr);
                }
                #pragma unroll
                for (int nj = 0; nj < 4; ++nj) {
                    uint32_t b[4];
                    int r = warp_n * 64 + nj * 16 + lrow;
                    uint32_t addr = sB + (uint32_t)(r * 128 + ((kc ^ (r & 7)) * 16));
                    ldsm_x4(b, addr);
                    #pragma unroll
                    for (int mi = 0; mi < 2; ++mi) {
                        imma16832(acc[mi][2 * nj],     a[mi], b[0], b[2]);
                        imma16832(acc[mi][2 * nj + 1], a[mi], b[1], b[3]);
                    }
                }
            }
        }
        __syncthreads();                       // stage kt+1 visible; WAR safe
    }

    // ---- epilogue phase 1: stage scaled pre-activations in smem ----
    // gcol == smem-B row rn (0..127): gate = rn>>5, col-in-gate = rn&31.
    float* __restrict__ pre_s = (float*)dyn;   // [128][PSTRIDE]
    const float* __restrict__ cmf = (const float*)g_cmax;
    if (wid < 8) {
        const int gid = lane >> 2, tig = lane & 3;
        #pragma unroll
        for (int mi = 0; mi < 2; ++mi) {
            int r0 = warp_m * 32 + mi * 16 + gid;
            float s0 = g_sa[m0 + r0] * SBSCALE;
            float s1 = g_sa[m0 + r0 + 8] * SBSCALE;
            #pragma unroll
            for (int nj = 0; nj < 8; ++nj) {
                int rn = warp_n * 64 + nj * 8 + tig * 2;
                float2 cm2;
                cm2.x = cmf[((rn >> 5) << 10) + col0 + (rn & 31)];
                cm2.y = cmf[(((rn + 1) >> 5) << 10) + col0 + ((rn + 1) & 31)];
                *(float2*)&pre_s[r0 * PSTRIDE + rn] =
                    make_float2(s0 * cm2.x * (float)acc[mi][nj][0],
                                s0 * cm2.y * (float)acc[mi][nj][1]);
                *(float2*)&pre_s[(r0 + 8) * PSTRIDE + rn] =
                    make_float2(s1 * cm2.x * (float)acc[mi][nj][2],
                                s1 * cm2.y * (float)acc[mi][nj][3]);
            }
        }
    }
    __syncthreads();

    // ---- epilogue phase 2: LSTM eltwise, write h_new ----
    if (tid < 256) {
        const int c4 = (tid & 7) * 4;          // column group 0..28
        float4 vbf = *(const float4*)&bf[col0 + c4];
        float4 vbi = *(const float4*)&bi[col0 + c4];
        float4 vbs = *(const float4*)&bs[col0 + c4];
        float4 vbp = *(const float4*)&bp[col0 + c4];
        const float* bfv = (const float*)&vbf;
        const float* biv = (const float*)&vbi;
        const float* bsv = (const float*)&vbs;
        const float* bpv = (const float*)&vbp;

        #pragma unroll
        for (int pass = 0; pass < 4; ++pass) {
            int rowl = (tid >> 3) + pass * 32;         // 0..127
            const float* rowp = pre_s + rowl * PSTRIDE;
            float4 pf = *(const float4*)&rowp[c4];          // gate 0 (forget)
            float4 pi = *(const float4*)&rowp[32 + c4];     // gate 1 (ignore)
            float4 ps = *(const float4*)&rowp[64 + c4];     // gate 2 (select)
            float4 pp = *(const float4*)&rowp[96 + c4];     // gate 3 (predict)
            float4 vc = *(const float4*)&cin[(size_t)(m0 + rowl) * 1024 + col0 + c4];

            const float* pfv = (const float*)&pf;
            const float* piv = (const float*)&pi;
            const float* psv = (const float*)&ps;
            const float* ppv = (const float*)&pp;
            const float* cv  = (const float*)&vc;

            float4 o; float* ov = (float*)&o;
            #pragma unroll
            for (int j = 0; j < 4; ++j) {
                float f = sigf(pfv[j] + bfv[j]);
                float i = sigf(piv[j] + biv[j]);
                float s = sigf(psv[j] + bsv[j]);
                float p = tanhfast(ppv[j] + bpv[j]);
                float cn = cv[j] * f + i * p;
                ov[j] = tanhfast(cn) * s;
            }
            *(float4*)&out[(size_t)(m0 + rowl) * 1024 + col0 + c4] = o;
        }
    }
}

// ---------------- launch ----------------
extern "C" void kernel_launch(void* const* d_in, const int* in_sizes, int n_in,
                              void* d_out, int out_size) {
    const float* x  = (const float*)d_in[0];
    const float* h  = (const float*)d_in[1];
    const float* c  = (const float*)d_in[2];
    const float* Wf = (const float*)d_in[3];
    const float* bf = (const float*)d_in[4];
    const float* Wi = (const float*)d_in[5];
    const float* bi = (const float*)d_in[6];
    const float* Ws = (const float*)d_in[7];
    const float* bs = (const float*)d_in[8];
    const float* Wp = (const float*)d_in[9];
    const float* bp = (const float*)d_in[10];
    float* out = (float*)d_out;

    cudaFuncSetAttribute(gemm_fused, cudaFuncAttributeMaxDynamicSharedMemorySize,
                         SMEM_DYN);

    quant_hx<<<4096, 256>>>(x, h);
    colmax_w<<<dim3(32, 8, 4), 256>>>(Wf, Wi, Ws, Wp);
    quant_w2<<<dim3(32, 32, 4), 256>>>(Wf, Wi, Ws, Wp);
    gemm_fused<<<dim3(32, 32), THREADS, SMEM_DYN>>>(c, bf, bi, bs, bp, out);
}

// round 15
// speedup vs baseline: 1.2910x; 1.2910x over previous
#include <cuda_runtime.h>
#include <math.h>
#include <stdint.h>

// LSTM cell B=4096, IN=H=1024 — int8 Karatsuba-Ozaki GEMM on IMMA m16n8k32,
// fused LSTM epilogue, 2 CTAs/SM (R11 mainloop — best measured, 213us).
// R15: (a) ks=0 computed before the kt+2 prefetch issue (first ldsm starts
// immediately post-barrier); (b) quant_hx + colmax_w merged into one launch
// (independent pass-1 kernels, overlapped DRAM traffic).
// Quantize: V = round(v * 2031 / scale), V = 17*D1 + D2 (|D1|<=119, |D2|<=8).
// Planes: S1 = D1, S2 = D1 + D2 (|S2| <= 127).
//   17*(16*P1 + P2) = V*W + 16*D2a*D2b   (dropped term ~2.5e-4 rel)
// GEMM tile: M=128 x N=128, N = same 32 output columns of all 4 gates
// (smem B row r <-> gate r>>5, col col0+(r&31)).

#define BM 128
#define BN 128
#define KTILES 32
#define STAGES 3
#define THREADS 256
#define A_STAGE_BYTES (BM * 128)        // 16384
#define B_STAGE_BYTES (BN * 128)        // 16384
#define STAGE_BYTES (A_STAGE_BYTES + B_STAGE_BYTES)   // 32768
#define SMEM_DYN (STAGES * STAGE_BYTES)               // 98304
#define PSTRIDE 132                     // floats per staged row (128 + pad)

#define VMAXF 2031.0f
#define SBSCALE (17.0f / (VMAXF * VMAXF))

static __device__ __align__(16) int8_t g_Aq[4096ull * 4096];  // [m][S1|S2]
static __device__ __align__(16) int8_t g_Bq[4096ull * 4096];  // [n=g*1024+c][T1|T2]
static __device__ float g_sa[4096];          // row max (raw)
static __device__ unsigned g_cmax[4096];     // col max |W| as float bits

// ---------------- PTX helpers (baseline sm_80 ISA) ----------------
__device__ __forceinline__ uint32_t smem_u32(const void* p) {
    return (uint32_t)__cvta_generic_to_shared(p);
}
__device__ __forceinline__ void cp16(uint32_t dst, const void* src) {
    asm volatile("cp.async.cg.shared.global [%0], [%1], 16;\n" :: "r"(dst), "l"(src));
}
__device__ __forceinline__ void cp_commit() {
    asm volatile("cp.async.commit_group;\n" ::: "memory");
}
#define CP_WAIT(N) asm volatile("cp.async.wait_group %0;\n" :: "n"(N) : "memory")

__device__ __forceinline__ void ldsm_x4(uint32_t* r, uint32_t addr) {
    asm volatile("ldmatrix.sync.aligned.m8n8.x4.shared.b16 {%0,%1,%2,%3}, [%4];\n"
                 : "=r"(r[0]), "=r"(r[1]), "=r"(r[2]), "=r"(r[3]) : "r"(addr));
}
__device__ __forceinline__ void imma16832(int* c, const uint32_t* a,
                                          uint32_t b0, uint32_t b1) {
    asm volatile(
        "mma.sync.aligned.m16n8k32.row.col.s32.s8.s8.s32 "
        "{%0,%1,%2,%3}, {%4,%5,%6,%7}, {%8,%9}, {%0,%1,%2,%3};\n"
        : "+r"(c[0]), "+r"(c[1]), "+r"(c[2]), "+r"(c[3])
        : "r"(a[0]), "r"(a[1]), "r"(a[2]), "r"(a[3]), "r"(b0), "r"(b1));
}

// Karatsuba digit split: S1 = D1, S2 = D1 + D2 for V = 17*D1 + D2.
__device__ __forceinline__ void kdigits(float val, float inv, char& s1, char& s2) {
    int vi = __float2int_rn(val * inv);                   // |vi| <= 2031
    int d1 = __float2int_rn((float)vi * (1.0f / 17.0f));  // |d1| <= 119
    int d2 = vi - 17 * d1;                                // |d2| <= 8
    s1 = (char)d1;
    s2 = (char)(d1 + d2);                                 // |.| <= 127
}

// Fast activations (MUFU-based, rel err ~1e-6, negligible vs 4.7e-4 quant).
__device__ __forceinline__ float sigf(float z) {
    return __fdividef(1.0f, 1.0f + __expf(-z));
}
__device__ __forceinline__ float tanhfast(float z) {
    return __fdividef(2.0f, 1.0f + __expf(-2.0f * z)) - 1.0f;
}

// ---------------- pass 1: activation quant + weight colmax (merged) ----------
// Blocks 0..4095: quantize hx row.  Blocks 4096..5119: column-max of W chunk.
__global__ __launch_bounds__(256)
void pass1(const float* __restrict__ x, const float* __restrict__ h,
           const float* __restrict__ Wf, const float* __restrict__ Wi,
           const float* __restrict__ Ws, const float* __restrict__ Wp) {
    if (blockIdx.x < 4096) {
        // -------- quant_hx (shuffle-reduce) --------
        __shared__ float wmax[8];
        const int m = blockIdx.x;
        const int t = threadIdx.x;
        const int lane = t & 31, wid = t >> 5;
        const float* src = (t < 128) ? (x + (size_t)m * 1024 + t * 8)
                                     : (h + (size_t)m * 1024 + (t - 128) * 8);
        float4 v0 = *(const float4*)src;
        float4 v1 = *(const float4*)(src + 4);
        float vals[8] = {v0.x, v0.y, v0.z, v0.w, v1.x, v1.y, v1.z, v1.w};
        float mx = 0.0f;
        #pragma unroll
        for (int j = 0; j < 8; ++j) mx = fmaxf(mx, fabsf(vals[j]));
        #pragma unroll
        for (int o = 16; o > 0; o >>= 1)
            mx = fmaxf(mx, __shfl_xor_sync(0xffffffffu, mx, o));
        if (lane == 0) wmax[wid] = mx;
        __syncthreads();
        float sa = wmax[0];
        #pragma unroll
        for (int j = 1; j < 8; ++j) sa = fmaxf(sa, wmax[j]);
        sa = fmaxf(sa, 1e-30f);
        if (t == 0) g_sa[m] = sa;
        const float inv = VMAXF / sa;
        char d1[8], d2[8];
        #pragma unroll
        for (int j = 0; j < 8; ++j) kdigits(vals[j], inv, d1[j], d2[j]);
        size_t base = (size_t)m * 4096 + t * 8;
        *(uint2*)&g_Aq[base]        = *(uint2*)d1;   // S1 plane
        *(uint2*)&g_Aq[base + 2048] = *(uint2*)d2;   // S2 plane
    } else {
        // -------- colmax_w --------
        __shared__ float red[8][33];
        const int bi = blockIdx.x - 4096;            // 0..1023
        const int g  = bi >> 8;                      // 0..3
        const int ky = (bi >> 5) & 7;                // 0..7
        const int nb = bi & 31;                      // 0..31
        const float* __restrict__ W =
            (g == 0) ? Wf : (g == 1) ? Wi : (g == 2) ? Ws : Wp;
        const int n0 = nb * 32;
        const int k0 = ky * 256;
        const int tx = threadIdx.x & 31;
        const int tk = threadIdx.x >> 5;             // 0..7

        float mx = 0.0f;
        #pragma unroll 8
        for (int i = 0; i < 32; ++i) {
            int k = k0 + tk + i * 8;
            mx = fmaxf(mx, fabsf(W[(size_t)k * 1024 + n0 + tx]));
        }
        red[tk][tx] = mx;
        __syncthreads();
        if (tk == 0) {
            float m = red[0][tx];
            #pragma unroll
            for (int j = 1; j < 8; ++j) m = fmaxf(m, red[j][tx]);
            atomicMax((int*)&g_cmax[g * 1024 + n0 + tx], __float_as_int(m));
        }
    }
}

// ---------------- pass 2: weight quantization ----------------
__global__ __launch_bounds__(256)
void quant_w2(const float* __restrict__ Wf, const float* __restrict__ Wi,
              const float* __restrict__ Ws, const float* __restrict__ Wp) {
    __shared__ __align__(8) char t1[32][64];
    __shared__ __align__(8) char t2[32][64];
    const int g = blockIdx.z;
    const float* __restrict__ W = (g == 0) ? Wf : (g == 1) ? Wi : (g == 2) ? Ws : Wp;
    const int n0 = blockIdx.x * 32;
    const int kt = blockIdx.y * 64;
    const int tx = threadIdx.x & 31;
    const int tk = threadIdx.x >> 5;   // 0..7

    const float cm = fmaxf(__int_as_float((int)g_cmax[g * 1024 + n0 + tx]), 1e-30f);
    const float inv = VMAXF / cm;

    #pragma unroll
    for (int j = 0; j < 8; ++j) {
        int k = kt + tk * 8 + j;
        char s1, s2;
        kdigits(W[(size_t)k * 1024 + n0 + tx], inv, s1, s2);
        t1[tx][tk * 8 + j] = s1;
        t2[tx][tk * 8 + j] = s2;
    }
    __syncthreads();
    const int r = threadIdx.x >> 3, seg = threadIdx.x & 7;
    size_t row = (size_t)(g * 1024 + n0 + r) * 4096;
    *(uint2*)&g_Bq[row + kt + seg * 8]        = *(uint2*)&t1[r][seg * 8];
    *(uint2*)&g_Bq[row + 2048 + kt + seg * 8] = *(uint2*)&t2[r][seg * 8];
}

// ---------------- fused IMMA GEMM + LSTM eltwise ----------------
__device__ __forceinline__ int koff(int kt) {
    return (kt < 16) ? (kt << 7) : (2048 + ((kt - 16) << 7));
}

__device__ __forceinline__ void load_stage(uint32_t sbase, int stage, int m0,
                                           int col0, int tid) {
    const uint32_t sb = sbase + (uint32_t)(stage % STAGES) * STAGE_BYTES;
    const int kk = koff(stage);
    #pragma unroll
    for (int j = 0; j < 4; ++j) {              // A: 128 rows x 128B = 1024 cp16
        int id = j * THREADS + tid;
        int r = id >> 3, c = id & 7;
        uint32_t dst = sb + (uint32_t)(r * 128 + ((c ^ (r & 7)) * 16));
        cp16(dst, g_Aq + ((size_t)(m0 + r) * 4096 + kk + c * 16));
    }
    #pragma unroll
    for (int j = 0; j < 4; ++j) {              // B: 128 rows x 128B = 1024 cp16
        int id = j * THREADS + tid;
        int r = id >> 3, c = id & 7;
        // smem row r <-> global B row: gate (r>>5), column col0 + (r&31)
        int nrow = ((r >> 5) << 10) + col0 + (r & 31);
        uint32_t dst = sb + (uint32_t)A_STAGE_BYTES
                     + (uint32_t)(r * 128 + ((c ^ (r & 7)) * 16));
        cp16(dst, g_Bq + ((size_t)nrow * 4096 + kk + c * 16));
    }
}

// One k32 step: load fragments and issue 16 IMMAs.
__device__ __forceinline__ void compute_ks(uint32_t sA, uint32_t sB, int warp_m,
                                           int warp_n, int lrow, int lhi, int ks,
                                           int acc[2][8][4]) {
    const int kc = ks * 2 + lhi;               // 16B chunk 0..7
    uint32_t a[2][4];
    #pragma unroll
    for (int mi = 0; mi < 2; ++mi) {
        int r = warp_m * 32 + mi * 16 + lrow;
        ldsm_x4(a[mi], sA + (uint32_t)(r * 128 + ((kc ^ (r & 7)) * 16)));
    }
    #pragma unroll
    for (int nj = 0; nj < 4; ++nj) {
        uint32_t b[4];
        int r = warp_n * 64 + nj * 16 + lrow;
        ldsm_x4(b, sB + (uint32_t)(r * 128 + ((kc ^ (r & 7)) * 16)));
        #pragma unroll
        for (int mi = 0; mi < 2; ++mi) {
            imma16832(acc[mi][2 * nj],     a[mi], b[0], b[2]);
            imma16832(acc[mi][2 * nj + 1], a[mi], b[1], b[3]);
        }
    }
}

__global__ __launch_bounds__(THREADS, 2)
void gemm_fused(const float* __restrict__ cin,
                const float* __restrict__ bf, const float* __restrict__ bi,
                const float* __restrict__ bs, const float* __restrict__ bp,
                float* __restrict__ out) {
    extern __shared__ char dyn[];
    const uint32_t sbase = smem_u32(dyn);

    const int tid = threadIdx.x;
    const int wid = tid >> 5;
    const int lane = tid & 31;
    const int warp_m = wid & 3;                // 4 slabs x 32 rows
    const int warp_n = wid >> 2;               // 0..1, 64-col slab
    const int m0 = blockIdx.y * BM;
    const int col0 = blockIdx.x * 32;          // output columns col0..col0+31

    const int lrow = lane & 15;
    const int lhi  = lane >> 4;

    int acc[2][8][4];
    #pragma unroll
    for (int mi = 0; mi < 2; ++mi)
        #pragma unroll
        for (int nj = 0; nj < 8; ++nj)
            #pragma unroll
            for (int q = 0; q < 4; ++q) acc[mi][nj][q] = 0;

    load_stage(sbase, 0, m0, col0, tid); cp_commit();
    load_stage(sbase, 1, m0, col0, tid); cp_commit();

    for (int kt = 0; kt < KTILES; ++kt) {
        CP_WAIT(1);
        __syncthreads();

        if (kt == 16) {                 // acc = 16*P1; continue with P2
            #pragma unroll
            for (int mi = 0; mi < 2; ++mi)
                #pragma unroll
                for (int nj = 0; nj < 8; ++nj)
                    #pragma unroll
                    for (int q = 0; q < 4; ++q) acc[mi][nj][q] <<= 4;
        }

        const uint32_t sA = sbase + (uint32_t)(kt % STAGES) * STAGE_BYTES;
        const uint32_t sB = sA + A_STAGE_BYTES;

        // ks=0 first: tensor work starts immediately after the barrier;
        // the kt+2 prefetch (WAR-safe since the barrier) is issued after it.
        compute_ks(sA, sB, warp_m, warp_n, lrow, lhi, 0, acc);

        if (kt + 2 < KTILES) load_stage(sbase, kt + 2, m0, col0, tid);
        cp_commit();

        #pragma unroll
        for (int ks = 1; ks < 4; ++ks)
            compute_ks(sA, sB, warp_m, warp_n, lrow, lhi, ks, acc);
    }

    // ---- epilogue phase 1: stage scaled pre-activations in smem ----
    // gcol == smem-B row rn (0..127): gate = rn>>5, col-in-gate = rn&31.
    __syncthreads();                           // all ldsm done; reuse pipeline smem
    float* __restrict__ pre_s = (float*)dyn;   // [128][PSTRIDE]
    const float* __restrict__ cmf = (const float*)g_cmax;
    {
        const int gid = lane >> 2, tig = lane & 3;
        #pragma unroll
        for (int mi = 0; mi < 2; ++mi) {
            int r0 = warp_m * 32 + mi * 16 + gid;
            float s0 = g_sa[m0 + r0] * SBSCALE;
            float s1 = g_sa[m0 + r0 + 8] * SBSCALE;
            #pragma unroll
            for (int nj = 0; nj < 8; ++nj) {
                int rn = warp_n * 64 + nj * 8 + tig * 2;
                float2 cm2;
                cm2.x = cmf[((rn >> 5) << 10) + col0 + (rn & 31)];
                cm2.y = cmf[(((rn + 1) >> 5) << 10) + col0 + ((rn + 1) & 31)];
                *(float2*)&pre_s[r0 * PSTRIDE + rn] =
                    make_float2(s0 * cm2.x * (float)acc[mi][nj][0],
                                s0 * cm2.y * (float)acc[mi][nj][1]);
                *(float2*)&pre_s[(r0 + 8) * PSTRIDE + rn] =
                    make_float2(s1 * cm2.x * (float)acc[mi][nj][2],
                                s1 * cm2.y * (float)acc[mi][nj][3]);
            }
        }
    }
    __syncthreads();

    // ---- epilogue phase 2: LSTM eltwise, write h_new ----
    {
        const int c4 = (tid & 7) * 4;          // column group 0..28
        float4 vbf = *(const float4*)&bf[col0 + c4];
        float4 vbi = *(const float4*)&bi[col0 + c4];
        float4 vbs = *(const float4*)&bs[col0 + c4];
        float4 vbp = *(const float4*)&bp[col0 + c4];
        const float* bfv = (const float*)&vbf;
        const float* biv = (const float*)&vbi;
        const float* bsv = (const float*)&vbs;
        const float* bpv = (const float*)&vbp;

        #pragma unroll
        for (int pass = 0; pass < 4; ++pass) {
            int rowl = (tid >> 3) + pass * 32;         // 0..127
            const float* rowp = pre_s + rowl * PSTRIDE;
            float4 pf = *(const float4*)&rowp[c4];          // gate 0 (forget)
            float4 pi = *(const float4*)&rowp[32 + c4];     // gate 1 (ignore)
            float4 ps = *(const float4*)&rowp[64 + c4];     // gate 2 (select)
            float4 pp = *(const float4*)&rowp[96 + c4];     // gate 3 (predict)
            float4 vc = *(const float4*)&cin[(size_t)(m0 + rowl) * 1024 + col0 + c4];

            const float* pfv = (const float*)&pf;
            const float* piv = (const float*)&pi;
            const float* psv = (const float*)&ps;
            const float* ppv = (const float*)&pp;
            const float* cv  = (const float*)&vc;

            float4 o; float* ov = (float*)&o;
            #pragma unroll
            for (int j = 0; j < 4; ++j) {
                float f = sigf(pfv[j] + bfv[j]);
                float i = sigf(piv[j] + biv[j]);
                float s = sigf(psv[j] + bsv[j]);
                float p = tanhfast(ppv[j] + bpv[j]);
                float cn = cv[j] * f + i * p;
                ov[j] = tanhfast(cn) * s;
            }
            *(float4*)&out[(size_t)(m0 + rowl) * 1024 + col0 + c4] = o;
        }
    }
}

// ---------------- launch ----------------
extern "C" void kernel_launch(void* const* d_in, const int* in_sizes, int n_in,
                              void* d_out, int out_size) {
    const float* x  = (const float*)d_in[0];
    const float* h  = (const float*)d_in[1];
    const float* c  = (const float*)d_in[2];
    const float* Wf = (const float*)d_in[3];
    const float* bf = (const float*)d_in[4];
    const float* Wi = (const float*)d_in[5];
    const float* bi = (const float*)d_in[6];
    const float* Ws = (const float*)d_in[7];
    const float* bs = (const float*)d_in[8];
    const float* Wp = (const float*)d_in[9];
    const float* bp = (const float*)d_in[10];
    float* out = (float*)d_out;

    cudaFuncSetAttribute(gemm_fused, cudaFuncAttributeMaxDynamicSharedMemorySize,
                         SMEM_DYN);

    pass1<<<5120, 256>>>(x, h, Wf, Wi, Ws, Wp);
    quant_w2<<<dim3(32, 32, 4), 256>>>(Wf, Wi, Ws, Wp);
    gemm_fused<<<dim3(32, 32), THREADS, SMEM_DYN>>>(c, bf, bi, bs, bp, out);
}